// round 1
// baseline (speedup 1.0000x reference)
#include <cuda_runtime.h>
#include <math.h>

// Problem constants (fixed shapes from setup_inputs)
#define FCN   16
#define WT    593          // (FC+2)*FC + FC + FC*FC + FC + FC + 1
#define H_    152
#define W_    272
#define HW_   41344
#define B_    4
#define M_    32
#define BM_   128
#define EPS_  1.0e-4f

#define THREADS 256
#define PIXB    2048
#define NTILES  ((HW_ + PIXB - 1) / PIXB)   // 21

// Scratch accumulators (no allocations allowed) — zeroed each launch by zero_acc.
__device__ double g_neg_acc;
__device__ double g_pos_acc;

__global__ void zero_acc_kernel() {
    g_neg_acc = 0.0;
    g_pos_acc = 0.0;
}

__global__ __launch_bounds__(THREADS)
void sch_loss_main(const float* __restrict__ sch_feat,
                   const float* __restrict__ conv_weight,
                   const float* __restrict__ mask,
                   const int*   __restrict__ pre_ind,
                   const float* __restrict__ target,
                   const int*   __restrict__ ind)
{
    __shared__ float sw[WT];
    __shared__ float sred[THREADS / 32];

    const int bm  = blockIdx.y;        // b*32 + m
    const int b   = bm >> 5;
    const int tid = threadIdx.x;
    const int pi  = pre_ind[bm];

    // Gather this (b,m)'s 593-float weight vector into shared.
    // conv_weight layout: (B, WT, H*W) contiguous.
    for (int c = tid; c < WT; c += THREADS)
        sw[c] = conv_weight[((long long)b * WT + c) * HW_ + pi];
    __syncthreads();

    const float* __restrict__ w1 = sw;          // [o*18 + c], 288 floats
    const float* __restrict__ b1 = sw + 288;    // 16
    const float* __restrict__ w2 = sw + 304;    // [o*16 + c], 256 floats
    const float* __restrict__ b2 = sw + 560;    // 16
    const float* __restrict__ w3 = sw + 576;    // 16
    const float  bias3           = sw[592];

    const float* __restrict__ sf = sch_feat + (long long)b * FCN * HW_;
    const float* __restrict__ tg = target   + (long long)bm * HW_;
    const int   posind = ind[bm];
    const float mval   = mask[bm];

    const float x0 = (float)(pi % W_);
    const float y0 = (float)pi / (float)W_;     // NOTE: float division, per reference
    const float inv128 = 1.0f / 128.0f;

    const int base  = blockIdx.x * PIXB;
    const int limit = (base + PIXB < HW_) ? (base + PIXB) : HW_;

    float negAcc = 0.0f;

    for (int p0 = base + tid; p0 < limit; p0 += 2 * THREADS) {
        const int  p1 = p0 + THREADS;
        const bool v1 = (p1 < limit);
        const int  p1c = v1 ? p1 : p0;   // clamp so loads stay in-bounds

        // ---- load features for two pixels ----
        float f0[FCN], f1[FCN];
        #pragma unroll
        for (int c = 0; c < FCN; ++c) {
            f0[c] = sf[c * HW_ + p0];
            f1[c] = sf[c * HW_ + p1c];
        }
        const float xr0 = ((float)(p0  % W_) - x0) * inv128;
        const float yr0 = ((float)(p0  / W_) - y0) * inv128;
        const float xr1 = ((float)(p1c % W_) - x0) * inv128;
        const float yr1 = ((float)(p1c / W_) - y0) * inv128;

        // ---- layer 1: 18 -> 16, relu ----
        float h0[FCN], h1[FCN];
        #pragma unroll
        for (int o = 0; o < FCN; ++o) {
            const float* __restrict__ w = w1 + o * 18;
            float a0 = b1[o];
            float a1 = a0;
            #pragma unroll
            for (int c = 0; c < FCN; ++c) {
                const float wv = w[c];
                a0 = fmaf(wv, f0[c], a0);
                a1 = fmaf(wv, f1[c], a1);
            }
            const float wx = w[16], wy = w[17];
            a0 = fmaf(wx, xr0, a0); a0 = fmaf(wy, yr0, a0);
            a1 = fmaf(wx, xr1, a1); a1 = fmaf(wy, yr1, a1);
            h0[o] = fmaxf(a0, 0.0f);
            h1[o] = fmaxf(a1, 0.0f);
        }

        // ---- layer 2: 16 -> 16, relu ----
        float g0[FCN], g1[FCN];
        #pragma unroll
        for (int o = 0; o < FCN; ++o) {
            const float* __restrict__ w = w2 + o * 16;
            float a0 = b2[o];
            float a1 = a0;
            #pragma unroll
            for (int c = 0; c < FCN; ++c) {
                const float wv = w[c];
                a0 = fmaf(wv, h0[c], a0);
                a1 = fmaf(wv, h1[c], a1);
            }
            g0[o] = fmaxf(a0, 0.0f);
            g1[o] = fmaxf(a1, 0.0f);
        }

        // ---- layer 3: 16 -> 1 ----
        float z0 = bias3, z1 = bias3;
        #pragma unroll
        for (int c = 0; c < FCN; ++c) {
            const float wv = w3[c];
            z0 = fmaf(wv, g0[c], z0);
            z1 = fmaf(wv, g1[c], z1);
        }

        // ---- sigmoid + clip + focal terms ----
        float hm0 = 1.0f / (1.0f + expf(-z0));
        hm0 = fminf(fmaxf(hm0, EPS_), 1.0f - EPS_);
        float q0 = 1.0f - tg[p0];
        q0 = q0 * q0; q0 = q0 * q0;                      // (1-t)^4
        negAcc += logf(1.0f - hm0) * hm0 * hm0 * q0;
        if (p0 == posind) {
            const float om = 1.0f - hm0;
            atomicAdd(&g_pos_acc, (double)(logf(hm0) * om * om * mval));
        }

        if (v1) {
            float hm1 = 1.0f / (1.0f + expf(-z1));
            hm1 = fminf(fmaxf(hm1, EPS_), 1.0f - EPS_);
            float q1 = 1.0f - tg[p1];
            q1 = q1 * q1; q1 = q1 * q1;
            negAcc += logf(1.0f - hm1) * hm1 * hm1 * q1;
            if (p1 == posind) {
                const float om = 1.0f - hm1;
                atomicAdd(&g_pos_acc, (double)(logf(hm1) * om * om * mval));
            }
        }
    }

    // ---- block reduction of negAcc, one double atomic per block ----
    #pragma unroll
    for (int off = 16; off > 0; off >>= 1)
        negAcc += __shfl_down_sync(0xFFFFFFFFu, negAcc, off);
    if ((tid & 31) == 0) sred[tid >> 5] = negAcc;
    __syncthreads();
    if (tid < 32) {
        float v = (tid < THREADS / 32) ? sred[tid] : 0.0f;
        #pragma unroll
        for (int off = 4; off > 0; off >>= 1)
            v += __shfl_down_sync(0xFFFFFFFFu, v, off);
        if (tid == 0) atomicAdd(&g_neg_acc, (double)v);
    }
}

__global__ void finalize_kernel(const float* __restrict__ mask, float* __restrict__ out)
{
    if (threadIdx.x == 0) {
        float np = 0.0f;
        for (int i = 0; i < BM_; ++i) np += mask[i];
        const double neg = g_neg_acc;
        const double pos = g_pos_acc;
        double loss;
        if (np == 0.0f) loss = -neg;
        else            loss = -(pos + neg) / (double)fmaxf(np, 1.0f);
        out[0] = (float)loss;
    }
}

extern "C" void kernel_launch(void* const* d_in, const int* in_sizes, int n_in,
                              void* d_out, int out_size)
{
    // metadata order: sch_feat, conv_weight, mask, pre_ind, target, ind
    const float* sch_feat    = (const float*)d_in[0];
    const float* conv_weight = (const float*)d_in[1];
    const float* mask        = (const float*)d_in[2];
    const int*   pre_ind     = (const int*)  d_in[3];
    const float* target      = (const float*)d_in[4];
    const int*   ind         = (const int*)  d_in[5];
    float* out = (float*)d_out;

    zero_acc_kernel<<<1, 1>>>();

    dim3 grid(NTILES, BM_);
    sch_loss_main<<<grid, THREADS>>>(sch_feat, conv_weight, mask, pre_ind, target, ind);

    finalize_kernel<<<1, 32>>>(mask, out);
}

// round 2
// speedup vs baseline: 1.2062x; 1.2062x over previous
#include <cuda_runtime.h>
#include <math.h>

// Fixed problem shapes
#define FCN   16
#define WT    593          // (FC+2)*FC + FC + FC*FC + FC + FC + 1
#define H_    152
#define W_    272
#define HW_   41344
#define B_    4
#define M_    32
#define BM_   128
#define EPS_  1.0e-4f

#define THREADS 128
#define PXPT    4                       // pixels per thread per iteration
#define PIXB    2048                    // pixels per block (4 iters of 512)
#define NTILES  ((HW_ + PIXB - 1) / PIXB)   // 21

// Scratch accumulators (allocations forbidden) — zeroed each launch.
__device__ double g_neg_acc;
__device__ double g_pos_acc;

__global__ void zero_acc_kernel() {
    g_neg_acc = 0.0;
    g_pos_acc = 0.0;
}

// ---- packed f32x2 helpers (Blackwell FFMA2 path) ----
typedef unsigned long long u64;

__device__ __forceinline__ u64 pack2(float lo, float hi) {
    u64 r;
    asm("mov.b64 %0, {%1, %2};" : "=l"(r) : "f"(lo), "f"(hi));
    return r;
}
__device__ __forceinline__ void unpack2(u64 v, float& lo, float& hi) {
    asm("mov.b64 {%0, %1}, %2;" : "=f"(lo), "=f"(hi) : "l"(v));
}
__device__ __forceinline__ u64 fma2(u64 a, u64 b, u64 c) {
    u64 d;
    asm("fma.rn.f32x2 %0, %1, %2, %3;" : "=l"(d) : "l"(a), "l"(b), "l"(c));
    return d;
}
__device__ __forceinline__ u64 relu2(u64 a) {
    float lo, hi;
    unpack2(a, lo, hi);
    lo = fmaxf(lo, 0.0f);
    hi = fmaxf(hi, 0.0f);
    return pack2(lo, hi);
}

__global__ __launch_bounds__(THREADS)
void sch_loss_main(const float* __restrict__ sch_feat,
                   const float* __restrict__ conv_weight,
                   const float* __restrict__ mask,
                   const int*   __restrict__ pre_ind,
                   const float* __restrict__ target,
                   const int*   __restrict__ ind)
{
    // Each weight stored duplicated: sdup[2i] = sdup[2i+1] = w[i].
    // One LDS.64 then yields a ready packed f32x2 multiplier.
    __shared__ __align__(16) float sdup[2 * WT];
    __shared__ float sred[THREADS / 32];

    const int bm  = blockIdx.y;        // b*32 + m
    const int b   = bm >> 5;
    const int tid = threadIdx.x;
    const int pi  = pre_ind[bm];

    // Gather 593-float weight vector (strided over conv_weight (B, WT, H*W)), duplicated.
    for (int c = tid; c < WT; c += THREADS) {
        const float v = conv_weight[((long long)b * WT + c) * HW_ + pi];
        sdup[2 * c]     = v;
        sdup[2 * c + 1] = v;
    }
    __syncthreads();

    const u64* __restrict__ swp = (const u64*)sdup;   // swp[i] = packed dup of weight i
    // weight index map: w1[o][c] = o*18+c ; b1[o]=288+o ; w2[o][c]=304+o*16+c ;
    //                   b2[o]=560+o ; w3[c]=576+c ; b3=592

    const float* __restrict__ sf = sch_feat + (long long)b * FCN * HW_;
    const float* __restrict__ tg = target   + (long long)bm * HW_;
    const int   posind = ind[bm];
    const float mval   = mask[bm];

    const float x0 = (float)(pi % W_);
    const float y0 = (float)pi / (float)W_;     // float division, matching reference
    const float inv128 = 1.0f / 128.0f;

    const int base  = blockIdx.x * PIXB;
    const int limit = (base + PIXB < HW_) ? (base + PIXB) : HW_;  // multiple of 4

    float negAcc = 0.0f;

    for (int p = base + PXPT * tid; p < limit; p += PXPT * THREADS) {
        // ---- features: pixels p..p+3 contiguous; one LDG.128 per channel.
        // halves of the 16B load are already packed f32x2 pairs (A = {p,p+1}, B = {p+2,p+3}).
        u64 fA[FCN], fB[FCN];
        #pragma unroll
        for (int c = 0; c < FCN; ++c) {
            const ulonglong2 v = *(const ulonglong2*)(sf + (long long)c * HW_ + p);
            fA[c] = v.x;
            fB[c] = v.y;
        }

        // relative coords: 272 % 4 == 0 ⇒ no row wrap inside the 4-pixel group
        const int   px = p % W_;
        const float yr = ((float)(p / W_) - y0) * inv128;
        const float xr0 = ((float)(px    ) - x0) * inv128;
        const float xr1 = ((float)(px + 1) - x0) * inv128;
        const float xr2 = ((float)(px + 2) - x0) * inv128;
        const float xr3 = ((float)(px + 3) - x0) * inv128;
        const u64 xrA = pack2(xr0, xr1);
        const u64 xrB = pack2(xr2, xr3);
        const u64 yrP = pack2(yr, yr);

        // ---- layer 1: 18 -> 16, relu (packed over 2 pixel-pairs) ----
        u64 hA[FCN], hB[FCN];
        #pragma unroll
        for (int o = 0; o < FCN; ++o) {
            const int wb = o * 18;
            u64 aA = swp[288 + o];     // bias (duplicated)
            u64 aB = aA;
            #pragma unroll
            for (int c = 0; c < FCN; ++c) {
                const u64 wp = swp[wb + c];
                aA = fma2(wp, fA[c], aA);
                aB = fma2(wp, fB[c], aB);
            }
            const u64 wx = swp[wb + 16];
            const u64 wy = swp[wb + 17];
            aA = fma2(wx, xrA, aA); aA = fma2(wy, yrP, aA);
            aB = fma2(wx, xrB, aB); aB = fma2(wy, yrP, aB);
            hA[o] = relu2(aA);
            hB[o] = relu2(aB);
        }

        // ---- layer 2: 16 -> 16, relu ----
        u64 gA[FCN], gB[FCN];
        #pragma unroll
        for (int o = 0; o < FCN; ++o) {
            const int wb = 304 + o * 16;
            u64 aA = swp[560 + o];
            u64 aB = aA;
            #pragma unroll
            for (int c = 0; c < FCN; ++c) {
                const u64 wp = swp[wb + c];
                aA = fma2(wp, hA[c], aA);
                aB = fma2(wp, hB[c], aB);
            }
            gA[o] = relu2(aA);
            gB[o] = relu2(aB);
        }

        // ---- layer 3: 16 -> 1 ----
        u64 zA = swp[592];
        u64 zB = zA;
        #pragma unroll
        for (int c = 0; c < FCN; ++c) {
            const u64 wp = swp[576 + c];
            zA = fma2(wp, gA[c], zA);
            zB = fma2(wp, gB[c], zB);
        }

        // ---- epilogue: sigmoid + clip + focal terms (scalar per pixel) ----
        float z[4];
        unpack2(zA, z[0], z[1]);
        unpack2(zB, z[2], z[3]);
        const float4 t4 = *(const float4*)(tg + p);
        const float tt[4] = {t4.x, t4.y, t4.z, t4.w};

        #pragma unroll
        for (int i = 0; i < 4; ++i) {
            float hm = 1.0f / (1.0f + __expf(-z[i]));
            hm = fminf(fmaxf(hm, EPS_), 1.0f - EPS_);
            float q = 1.0f - tt[i];
            q = q * q; q = q * q;                       // (1-t)^4
            negAcc += __logf(1.0f - hm) * hm * hm * q;
            if (p + i == posind) {
                const float om = 1.0f - hm;
                atomicAdd(&g_pos_acc, (double)(__logf(hm) * om * om * mval));
            }
        }
    }

    // ---- block reduction, one double atomic per block ----
    #pragma unroll
    for (int off = 16; off > 0; off >>= 1)
        negAcc += __shfl_down_sync(0xFFFFFFFFu, negAcc, off);
    if ((tid & 31) == 0) sred[tid >> 5] = negAcc;
    __syncthreads();
    if (tid < 32) {
        float v = (tid < THREADS / 32) ? sred[tid] : 0.0f;
        #pragma unroll
        for (int off = 2; off > 0; off >>= 1)
            v += __shfl_down_sync(0xFFFFFFFFu, v, off);
        if (tid == 0) atomicAdd(&g_neg_acc, (double)v);
    }
}

__global__ void finalize_kernel(const float* __restrict__ mask, float* __restrict__ out)
{
    if (threadIdx.x == 0) {
        float np = 0.0f;
        for (int i = 0; i < BM_; ++i) np += mask[i];
        const double neg = g_neg_acc;
        const double pos = g_pos_acc;
        double loss;
        if (np == 0.0f) loss = -neg;
        else            loss = -(pos + neg) / (double)fmaxf(np, 1.0f);
        out[0] = (float)loss;
    }
}

extern "C" void kernel_launch(void* const* d_in, const int* in_sizes, int n_in,
                              void* d_out, int out_size)
{
    const float* sch_feat    = (const float*)d_in[0];
    const float* conv_weight = (const float*)d_in[1];
    const float* mask        = (const float*)d_in[2];
    const int*   pre_ind     = (const int*)  d_in[3];
    const float* target      = (const float*)d_in[4];
    const int*   ind         = (const int*)  d_in[5];
    float* out = (float*)d_out;

    zero_acc_kernel<<<1, 1>>>();

    dim3 grid(NTILES, BM_);
    sch_loss_main<<<grid, THREADS>>>(sch_feat, conv_weight, mask, pre_ind, target, ind);

    finalize_kernel<<<1, 32>>>(mask, out);
}